// round 6
// baseline (speedup 1.0000x reference)
#include <cuda_runtime.h>
#include <math.h>

#define N 8192
#define D 64
#define ALPHA 0.2f
#define NB 16384
#define SHIFT 18           // bucket = top 14 bits of order-flipped float key
#define NBLK 130
#define NTHR 1024
#define GSIZE (NBLK * NTHR)

// ---------------- scratch (device globals; no allocation allowed) -----------
__device__ float    g_h[N * D];        // projected features (2 MB)
__device__ float    g_f1[N];
__device__ float    g_f2[N];
__device__ unsigned g_ukey[N];
__device__ __align__(16) int g_hist[NB];
__device__ int      g_start[NB + 1];
__device__ int      g_cursor[NB];
__device__ unsigned g_bkey[N];
__device__ int      g_bidx[N];
__device__ float    g_f2s[N];          // f2 sorted ascending
__device__ int      g_ord[N];          // sorted position -> original index
__device__ float    g_ehi[N];          // e^{f2s}
__device__ float    g_elo[N];          // e^{ALPHA*f2s}
__device__ int      g_p[N];            // per-row split point
__device__ float    g_c[N];            // per-row e^{(ALPHA-1) f1}
__device__ double   g_PartHi[65 * 128];// per-block partial sums (dim 64 = scalar)
__device__ double   g_PartLo[65 * 128];
__device__ double   g_OffHi[65 * 128]; // exclusive block offsets
__device__ double   g_OffLo[65 * 128];
__device__ double   g_Phi[N * D];      // inclusive prefix of e^{f2} h, [k][d]
__device__ double   g_Plo[N * D];      // inclusive prefix of e^{a f2} h, [k][d]
__device__ double   g_pshi[N];
__device__ double   g_pslo[N];

// ---------------- software grid barrier -------------------------------------
__device__ unsigned g_bar_arrive = 0;
__device__ unsigned g_bar_gen    = 0;

__device__ __forceinline__ void gbar(unsigned& gen) {
    __syncthreads();
    if (threadIdx.x == 0) {
        __threadfence();
        unsigned my = gen;
        if (atomicAdd(&g_bar_arrive, 1) == NBLK - 1) {
            g_bar_arrive = 0;
            __threadfence();
            atomicAdd(&g_bar_gen, 1);
        } else {
            while (*(volatile unsigned*)&g_bar_gen == my) __nanosleep(32);
        }
        __threadfence();
        gen = my + 1;
    }
    __syncthreads();
}

// ---------------- the single persistent kernel ------------------------------
__global__ void __launch_bounds__(NTHR, 1) k_fused(
    const float* __restrict__ x,  const float* __restrict__ Wt,
    const float* __restrict__ a1, const float* __restrict__ b1,
    const float* __restrict__ a2, const float* __restrict__ b2,
    float* __restrict__ out)
{
    __shared__ __align__(16) char sbuf[35328];

    const int t    = threadIdx.x;
    const int b    = blockIdx.x;
    const int gtid = b * NTHR + t;
    const int lane = t & 31, warp = t >> 5;
    unsigned gen = *(volatile unsigned*)&g_bar_gen;   // per-launch snapshot

    // ===== Phase A: projection (4 rows/thread, transposed W) + scores =======
    if (b < 128) {
        float* sWtT  = (float*)sbuf;                  // [64][68] padded
        float* sx    = (float*)(sbuf + 17408);        // [64][64]
        float* sa1   = (float*)(sbuf + 33792);
        float* sa2   = (float*)(sbuf + 34048);
        float* sred1 = (float*)(sbuf + 34304);        // [32 warps][4 rows]
        float* sred2 = (float*)(sbuf + 34816);
        const int row0 = b * 64;

        for (int i = t; i < 4096; i += NTHR) {
            int k = i >> 6, dd = i & 63;
            sWtT[dd * 68 + k] = Wt[i];                // Wt[k][d] -> WtT[d][k]
        }
        for (int i = t; i < 4096; i += NTHR) sx[i] = x[row0 * 64 + i];
        if (t < 64) { sa1[t] = a1[t]; sa2[t] = a2[t]; }
        __syncthreads();

        const int d = t & 63, rg = t >> 6;
        const float* xr = sx + rg * 4 * 64;
        float acc0 = 0.f, acc1 = 0.f, acc2 = 0.f, acc3 = 0.f;
        #pragma unroll 4
        for (int kk = 0; kk < 64; kk += 4) {
            float4 wv = *(const float4*)&sWtT[d * 68 + kk];
            float4 x0 = *(const float4*)&xr[0 * 64 + kk];
            float4 x1 = *(const float4*)&xr[1 * 64 + kk];
            float4 x2 = *(const float4*)&xr[2 * 64 + kk];
            float4 x3 = *(const float4*)&xr[3 * 64 + kk];
            acc0 = fmaf(x0.x, wv.x, fmaf(x0.y, wv.y, fmaf(x0.z, wv.z, fmaf(x0.w, wv.w, acc0))));
            acc1 = fmaf(x1.x, wv.x, fmaf(x1.y, wv.y, fmaf(x1.z, wv.z, fmaf(x1.w, wv.w, acc1))));
            acc2 = fmaf(x2.x, wv.x, fmaf(x2.y, wv.y, fmaf(x2.z, wv.z, fmaf(x2.w, wv.w, acc2))));
            acc3 = fmaf(x3.x, wv.x, fmaf(x3.y, wv.y, fmaf(x3.z, wv.z, fmaf(x3.w, wv.w, acc3))));
        }
        const int r0 = rg * 4;
        g_h[(row0 + r0 + 0) * 64 + d] = acc0;
        g_h[(row0 + r0 + 1) * 64 + d] = acc1;
        g_h[(row0 + r0 + 2) * 64 + d] = acc2;
        g_h[(row0 + r0 + 3) * 64 + d] = acc3;

        float a1d = sa1[d], a2d = sa2[d];
        float q10 = acc0 * a1d, q11 = acc1 * a1d, q12 = acc2 * a1d, q13 = acc3 * a1d;
        float q20 = acc0 * a2d, q21 = acc1 * a2d, q22 = acc2 * a2d, q23 = acc3 * a2d;
        #pragma unroll
        for (int off = 16; off > 0; off >>= 1) {
            q10 += __shfl_down_sync(0xffffffffu, q10, off);
            q11 += __shfl_down_sync(0xffffffffu, q11, off);
            q12 += __shfl_down_sync(0xffffffffu, q12, off);
            q13 += __shfl_down_sync(0xffffffffu, q13, off);
            q20 += __shfl_down_sync(0xffffffffu, q20, off);
            q21 += __shfl_down_sync(0xffffffffu, q21, off);
            q22 += __shfl_down_sync(0xffffffffu, q22, off);
            q23 += __shfl_down_sync(0xffffffffu, q23, off);
        }
        if (lane == 0) {
            sred1[warp * 4 + 0] = q10; sred1[warp * 4 + 1] = q11;
            sred1[warp * 4 + 2] = q12; sred1[warp * 4 + 3] = q13;
            sred2[warp * 4 + 0] = q20; sred2[warp * 4 + 1] = q21;
            sred2[warp * 4 + 2] = q22; sred2[warp * 4 + 3] = q23;
        }
        __syncthreads();
        if (t < 64) {
            int rg2 = t >> 2, rr = t & 3;
            int w0 = rg2 * 2, w1 = w0 + 1;
            float f1v = sred1[w0 * 4 + rr] + sred1[w1 * 4 + rr] + b1[0];
            float f2v = sred2[w0 * 4 + rr] + sred2[w1 * 4 + rr] + b2[0];
            int row = row0 + t;
            g_f1[row] = f1v;
            g_f2[row] = f2v;
            unsigned u = __float_as_uint(f2v);
            u ^= (u >> 31) ? 0xFFFFFFFFu : 0x80000000u;
            g_ukey[row] = u;
            atomicAdd(&g_hist[u >> SHIFT], 1);
        }
    }
    gbar(gen);

    // ===== Phase B: full histogram exclusive scan, ONE block ================
    if (b == 0) {
        int* sint = (int*)sbuf;
        int base = t * 16;
        int loc[16];
        int sum = 0;
        const uint4* H4 = (const uint4*)(g_hist + base);
        #pragma unroll
        for (int q = 0; q < 4; q++) {
            uint4 hv = H4[q];
            loc[q * 4 + 0] = sum; sum += (int)hv.x;
            loc[q * 4 + 1] = sum; sum += (int)hv.y;
            loc[q * 4 + 2] = sum; sum += (int)hv.z;
            loc[q * 4 + 3] = sum; sum += (int)hv.w;
        }
        int w = sum;
        #pragma unroll
        for (int off = 1; off < 32; off <<= 1) {
            int o = __shfl_up_sync(0xffffffffu, w, off);
            if (lane >= off) w += o;
        }
        if (lane == 31) sint[warp] = w;
        __syncthreads();
        if (t < 32) {
            int v = sint[t];
            #pragma unroll
            for (int off = 1; off < 32; off <<= 1) {
                int o = __shfl_up_sync(0xffffffffu, v, off);
                if (t >= off) v += o;
            }
            sint[t] = v;
        }
        __syncthreads();
        int excl = (w - sum) + (warp ? sint[warp - 1] : 0);
        #pragma unroll
        for (int j = 0; j < 16; j++) {
            int s = excl + loc[j];
            g_start[base + j]  = s;
            g_cursor[base + j] = s;
        }
        if (t == 0) g_start[NB] = N;
    }
    gbar(gen);

    // ===== Phase C: scatter (128 blocks x 64) + re-zero histogram ===========
    if (b < 128) {
        if (t < 64) {
            int i = b * 64 + t;
            unsigned u = g_ukey[i];
            int pos = atomicAdd(&g_cursor[u >> SHIFT], 1);
            g_bkey[pos] = u;
            g_bidx[pos] = i;
        } else if (t < 192) {
            g_hist[b * 128 + (t - 64)] = 0;
        }
    }
    gbar(gen);

    // ===== Phase D: rank within bucket (16 threads/element, all blocks) =====
    if (b < 128) {
        int el = b * 64 + (t >> 4), seg = t & 15;
        unsigned u = g_bkey[el];
        int i  = g_bidx[el];
        int bk = u >> SHIFT;
        int st = g_start[bk], en = g_start[bk + 1];
        int rank = 0;
        for (int j = st + seg; j < en; j += 16) {
            unsigned kj = g_bkey[j];
            rank += (kj < u) || (kj == u && g_bidx[j] < i);
        }
        #pragma unroll
        for (int off = 8; off > 0; off >>= 1)
            rank += __shfl_down_sync(0xffffffffu, rank, off, 16);
        if (seg == 0) {
            rank += st;
            float f2v = g_f2[i];
            g_f2s[rank] = f2v;
            g_ord[rank] = i;
            g_ehi[rank] = expf(f2v);
            g_elo[rank] = expf(ALPHA * f2v);
        }
    }
    gbar(gen);

    // ===== Phase E1: per-block partial sums (coalesced), group exclusives ===
    double* sgh = (double*)sbuf;           // [16][64]
    double* sgl = sgh + 1024;              // [16][64]
    double* seh = sgl + 1024;              // [16]
    double* sel = seh + 16;                // [16]
    {
        const int d = t & 63, rg = t >> 6;
        if (b < 128) {
            const int k0 = b * 64 + rg * 4;
            double ah = 0.0, al = 0.0, sh = 0.0, sl = 0.0;
            #pragma unroll
            for (int rr = 0; rr < 4; rr++) {
                int k = k0 + rr;
                int o = g_ord[k];
                float eh = g_ehi[k], ev = g_elo[k];
                float hv = g_h[o * 64 + d];
                ah += (double)eh * hv;
                al += (double)ev * hv;
                if (d == 0) { sh += (double)eh; sl += (double)ev; }
            }
            sgh[rg * 64 + d] = ah;
            sgl[rg * 64 + d] = al;
            if (d == 0) { seh[rg] = sh; sel[rg] = sl; }
            __syncthreads();
            if (t < 64) {
                double run = 0.0;
                #pragma unroll
                for (int j = 0; j < 16; j++) { double v = sgh[j * 64 + t]; sgh[j * 64 + t] = run; run += v; }
                g_PartHi[t * 128 + b] = run;
                run = 0.0;
                #pragma unroll
                for (int j = 0; j < 16; j++) { double v = sgl[j * 64 + t]; sgl[j * 64 + t] = run; run += v; }
                g_PartLo[t * 128 + b] = run;
            } else if (t == 64) {
                double run = 0.0;
                #pragma unroll
                for (int j = 0; j < 16; j++) { double v = seh[j]; seh[j] = run; run += v; }
                g_PartHi[64 * 128 + b] = run;
                run = 0.0;
                #pragma unroll
                for (int j = 0; j < 16; j++) { double v = sel[j]; sel[j] = run; run += v; }
                g_PartLo[64 * 128 + b] = run;
            }
        }
    }
    gbar(gen);

    // ===== Phase E2: block-offset scans (warp 0 of each block) + psearch ====
    {
        if (t < 32) {
            const double* P = (b < 65) ? (g_PartHi + b * 128) : (g_PartLo + (b - 65) * 128);
            double*       O = (b < 65) ? (g_OffHi  + b * 128) : (g_OffLo  + (b - 65) * 128);
            double v0 = P[t * 4 + 0], v1 = P[t * 4 + 1], v2 = P[t * 4 + 2], v3 = P[t * 4 + 3];
            double sum = v0 + v1 + v2 + v3;
            double w = sum;
            #pragma unroll
            for (int off = 1; off < 32; off <<= 1) {
                double o = __shfl_up_sync(0xffffffffu, w, off);
                if (t >= off) w += o;
            }
            double r = w - sum;            // exclusive base
            O[t * 4 + 0] = r; r += v0;
            O[t * 4 + 1] = r; r += v1;
            O[t * 4 + 2] = r; r += v2;
            O[t * 4 + 3] = r;
        } else if (t < 96 && b < 128) {
            int row = b * 64 + (t - 32);
            float f1 = g_f1[row];
            float tt = -f1;
            int lo = 0, hi2 = N;           // p = #{ f2s <= -f1 }
            while (lo < hi2) {
                int mid = (lo + hi2) >> 1;
                if (g_f2s[mid] <= tt) lo = mid + 1; else hi2 = mid;
            }
            g_p[row] = lo;
            g_c[row] = expf((ALPHA - 1.0f) * f1);
        }
    }
    gbar(gen);

    // ===== Phase E3: final prefix store, fully coalesced ====================
    if (b < 128) {
        const int d = t & 63, rg = t >> 6;
        const int k0 = b * 64 + rg * 4;
        double rh = g_OffHi[d * 128 + b] + sgh[rg * 64 + d];   // smem persisted
        double rl = g_OffLo[d * 128 + b] + sgl[rg * 64 + d];
        double rsh = 0.0, rsl = 0.0;
        if (d == 0) {
            rsh = g_OffHi[64 * 128 + b] + seh[rg];
            rsl = g_OffLo[64 * 128 + b] + sel[rg];
        }
        #pragma unroll
        for (int rr = 0; rr < 4; rr++) {
            int k = k0 + rr;
            int o = g_ord[k];
            float eh = g_ehi[k], ev = g_elo[k];
            float hv = g_h[o * 64 + d];
            rh += (double)eh * hv;  g_Phi[k * 64 + d] = rh;
            rl += (double)ev * hv;  g_Plo[k * 64 + d] = rl;
            if (d == 0) {
                rsh += (double)eh;  g_pshi[k] = rsh;
                rsl += (double)ev;  g_pslo[k] = rsl;
            }
        }
    }
    gbar(gen);

    // ===== Phase G: combine + ELU ===========================================
    {
        const int d = gtid & 63;           // invariant: GSIZE % 64 == 0
        double toth = g_Phi[(N - 1) * 64 + d];
        double tosh = g_pshi[N - 1];
        for (int idx = gtid; idx < N * D; idx += GSIZE) {
            int row = idx >> 6;
            int   p = g_p[row];
            float c = g_c[row];
            double num = toth, den = tosh;
            if (p > 0) {
                num = num - g_Phi[(p - 1) * 64 + d] + (double)c * g_Plo[(p - 1) * 64 + d];
                den = den - g_pshi[p - 1] + (double)c * g_pslo[p - 1];
            }
            float v = __fdividef((float)num, (float)den);
            out[idx] = (v > 0.f) ? v : expm1f(v);
        }
    }
}

// ---------------- launch ----------------------------------------------------
extern "C" void kernel_launch(void* const* d_in, const int* in_sizes, int n_in,
                              void* d_out, int out_size) {
    const float* x  = (const float*)d_in[0];
    const float* Wt = (const float*)d_in[1];
    const float* a1 = (const float*)d_in[2];
    const float* b1 = (const float*)d_in[3];
    const float* a2 = (const float*)d_in[4];
    const float* b2 = (const float*)d_in[5];
    float* out = (float*)d_out;

    k_fused<<<NBLK, NTHR>>>(x, Wt, a1, b1, a2, b2, out);
}

// round 7
// speedup vs baseline: 1.0121x; 1.0121x over previous
#include <cuda_runtime.h>
#include <math.h>

#define N 8192
#define D 64
#define ALPHA 0.2f
#define NB 16384
#define SHIFT 18           // bucket = top 14 bits of order-flipped float key
#define NBLK 148
#define NTHR 1024
#define GSIZE (NBLK * NTHR)

// ---------------- scratch (device globals; no allocation allowed) -----------
__device__ float    g_h[N * D];        // projected features (2 MB)
__device__ float    g_hsT[D * N];      // h, sorted order, TRANSPOSED [d][k] (2 MB)
__device__ float    g_f1[N];
__device__ float    g_f2[N];
__device__ unsigned g_ukey[N];
__device__ __align__(16) int g_hist[NB];
__device__ int      g_start[NB + 1];
__device__ int      g_cursor[NB];
__device__ unsigned g_bkey[N];
__device__ int      g_bidx[N];
__device__ float    g_f2s[N];          // f2 sorted ascending
__device__ float    g_ehi[N];          // e^{f2s}
__device__ float    g_elo[N];          // e^{ALPHA*f2s}
__device__ int      g_p[N];            // per-row split point
__device__ float    g_c[N];            // per-row e^{(ALPHA-1) f1}
__device__ double   g_Phi[N * D];      // inclusive prefix of e^{f2} h, [k][d]
__device__ double   g_Plo[N * D];      // inclusive prefix of e^{a f2} h, [k][d]
__device__ double   g_pshi[N];
__device__ double   g_pslo[N];

// ---------------- software grid barrier -------------------------------------
__device__ unsigned g_bar_arrive = 0;
__device__ unsigned g_bar_gen    = 0;

__device__ __forceinline__ void gbar(unsigned& gen) {
    __syncthreads();
    if (threadIdx.x == 0) {
        __threadfence();
        unsigned my = gen;
        if (atomicAdd(&g_bar_arrive, 1) == NBLK - 1) {
            g_bar_arrive = 0;          // reset BEFORE release (ordered by fence)
            __threadfence();
            atomicAdd(&g_bar_gen, 1);
        } else {
            while (*(volatile unsigned*)&g_bar_gen == my) __nanosleep(32);
        }
        __threadfence();
        gen = my + 1;
    }
    __syncthreads();
}

// ---------------- the single persistent kernel ------------------------------
__global__ void __launch_bounds__(NTHR, 1) k_fused(
    const float* __restrict__ x,  const float* __restrict__ Wt,
    const float* __restrict__ a1, const float* __restrict__ b1,
    const float* __restrict__ a2, const float* __restrict__ b2,
    float* __restrict__ out)
{
    __shared__ float  sWt[D * D];      // 16 KB
    __shared__ float  sx[16 * D];      // 4 KB
    __shared__ float  sa1[D], sa2[D];
    __shared__ float  sred1[32], sred2[32];
    __shared__ int    sint[32];
    __shared__ double sdbl[32];

    const int t    = threadIdx.x;
    const int b    = blockIdx.x;
    const int gtid = b * NTHR + t;
    const int lane = t & 31, warp = t >> 5;
    unsigned gen = *(volatile unsigned*)&g_bar_gen;   // per-launch snapshot

    // ===== Phase A: projection h = x*Wt, scores f1/f2, key + histogram ======
    if (b < 128) {
        for (int i = t; i < D * D; i += NTHR) sWt[i] = Wt[i];
        if (t < D) { sa1[t] = a1[t]; sa2[t] = a2[t]; }
        const int r = t >> 6;          // 0..15 local row
        const int d = t & 63;
        for (int chunk = 0; chunk < 4; chunk++) {
            const int row0 = b * 64 + chunk * 16;
            __syncthreads();           // protect sx reuse (and sWt on chunk 0)
            for (int i = t; i < 16 * D; i += NTHR) sx[i] = x[row0 * D + i];
            __syncthreads();
            float h = 0.f;
            #pragma unroll
            for (int k = 0; k < D; k += 4) {
                float4 xv = *(const float4*)&sx[r * D + k];
                h = fmaf(xv.x, sWt[(k + 0) * D + d], h);
                h = fmaf(xv.y, sWt[(k + 1) * D + d], h);
                h = fmaf(xv.z, sWt[(k + 2) * D + d], h);
                h = fmaf(xv.w, sWt[(k + 3) * D + d], h);
            }
            g_h[(row0 + r) * D + d] = h;

            float p1 = h * sa1[d];
            float p2 = h * sa2[d];
            #pragma unroll
            for (int off = 16; off > 0; off >>= 1) {
                p1 += __shfl_down_sync(0xffffffffu, p1, off);
                p2 += __shfl_down_sync(0xffffffffu, p2, off);
            }
            if (lane == 0) { sred1[warp] = p1; sred2[warp] = p2; }
            __syncthreads();
            if (t < 16) {
                float f1  = sred1[2 * t] + sred1[2 * t + 1] + b1[0];
                float f2v = sred2[2 * t] + sred2[2 * t + 1] + b2[0];
                int row = row0 + t;
                g_f1[row] = f1;
                g_f2[row] = f2v;
                unsigned u = __float_as_uint(f2v);
                u ^= (u >> 31) ? 0xFFFFFFFFu : 0x80000000u;
                g_ukey[row] = u;
                atomicAdd(&g_hist[u >> SHIFT], 1);
            }
        }
    }
    gbar(gen);

    // ===== Phase B: full histogram exclusive scan, ONE block ================
    if (b == 0) {
        int base = t * 16;
        int loc[16];
        int sum = 0;
        const uint4* H4 = (const uint4*)(g_hist + base);
        #pragma unroll
        for (int q = 0; q < 4; q++) {
            uint4 hv = H4[q];
            loc[q * 4 + 0] = sum; sum += (int)hv.x;
            loc[q * 4 + 1] = sum; sum += (int)hv.y;
            loc[q * 4 + 2] = sum; sum += (int)hv.z;
            loc[q * 4 + 3] = sum; sum += (int)hv.w;
        }
        int w = sum;
        #pragma unroll
        for (int off = 1; off < 32; off <<= 1) {
            int o = __shfl_up_sync(0xffffffffu, w, off);
            if (lane >= off) w += o;
        }
        if (lane == 31) sint[warp] = w;
        __syncthreads();
        if (t < 32) {
            int v = sint[t];
            #pragma unroll
            for (int off = 1; off < 32; off <<= 1) {
                int o = __shfl_up_sync(0xffffffffu, v, off);
                if (t >= off) v += o;
            }
            sint[t] = v;
        }
        __syncthreads();
        int excl = (w - sum) + (warp ? sint[warp - 1] : 0);
        #pragma unroll
        for (int j = 0; j < 16; j++) {
            int s = excl + loc[j];
            g_start[base + j]  = s;
            g_cursor[base + j] = s;
        }
        if (t == 0) g_start[NB] = N;
    }
    gbar(gen);

    // ===== Phase C: scatter into buckets; spare blocks re-zero histogram ====
    if (gtid < N) {
        unsigned u = g_ukey[gtid];
        int pos = atomicAdd(&g_cursor[u >> SHIFT], 1);
        g_bkey[pos] = u;
        g_bidx[pos] = gtid;
    } else if (gtid - N < NB) {
        g_hist[gtid - N] = 0;
    }
    gbar(gen);

    // ===== Phase D: rank within bucket (16 thr/elem) + fused transpose ======
    if (b < 128) {
        int el = b * 64 + (t >> 4), seg = t & 15;
        unsigned u = g_bkey[el];
        int i  = g_bidx[el];
        int bk = u >> SHIFT;
        int st = g_start[bk], en = g_start[bk + 1];
        int rank = 0;
        for (int j = st + seg; j < en; j += 16) {
            unsigned kj = g_bkey[j];
            rank += (kj < u) || (kj == u && g_bidx[j] < i);
        }
        #pragma unroll
        for (int off = 8; off > 0; off >>= 1)
            rank += __shfl_down_sync(0xffffffffu, rank, off, 16);
        rank = __shfl_sync(0xffffffffu, rank, 0, 16);   // broadcast within 16-group
        rank += st;
        if (seg == 0) {
            float f2v = g_f2[i];
            g_f2s[rank] = f2v;
            g_ehi[rank] = expf(f2v);
            g_elo[rank] = expf(ALPHA * f2v);
        }
        float4 hv = *(const float4*)&g_h[i * D + seg * 4];
        g_hsT[(seg * 4 + 0) * N + rank] = hv.x;
        g_hsT[(seg * 4 + 1) * N + rank] = hv.y;
        g_hsT[(seg * 4 + 2) * N + rank] = hv.z;
        g_hsT[(seg * 4 + 3) * N + rank] = hv.w;
    }
    gbar(gen);

    // ===== Phase E: 130 inclusive fp64 scans (one per block) + psearch ======
    if (b < 130) {
        bool scalar = (b >= 128);
        bool hi = (b < 64) || (b == 128);
        int dim = scalar ? 0 : (hi ? b : b - 64);
        const float* e    = hi ? g_ehi : g_elo;
        const float* hrow = g_hsT + (size_t)dim * N;

        int k0 = t * 8;
        double v[8];
        double run = 0.0;
        #pragma unroll
        for (int j = 0; j < 8; j++) {
            double val = (double)e[k0 + j];
            if (!scalar) val *= (double)hrow[k0 + j];
            run += val;
            v[j] = run;
        }
        double w = run;
        #pragma unroll
        for (int off = 1; off < 32; off <<= 1) {
            double o = __shfl_up_sync(0xffffffffu, w, off);
            if (lane >= off) w += o;
        }
        if (lane == 31) sdbl[warp] = w;
        __syncthreads();
        if (t < 32) {
            double x2 = sdbl[t];
            #pragma unroll
            for (int off = 1; off < 32; off <<= 1) {
                double o = __shfl_up_sync(0xffffffffu, x2, off);
                if (t >= off) x2 += o;
            }
            sdbl[t] = x2;
        }
        __syncthreads();
        double base = (w - run) + (warp ? sdbl[warp - 1] : 0.0);

        if (scalar) {
            double* o = hi ? g_pshi : g_pslo;
            #pragma unroll
            for (int j = 0; j < 8; j++) o[k0 + j] = base + v[j];
        } else {
            double* o = hi ? g_Phi : g_Plo;
            #pragma unroll
            for (int j = 0; j < 8; j++) o[(k0 + j) * D + dim] = base + v[j];
        }

        // per-row binary search (idle-lane work, independent of scan stores)
        if (t < 64 && b < 128) {
            int row = b * 64 + t;
            float f1 = g_f1[row];
            float tt = -f1;
            int lo = 0, hi2 = N;           // p = #{ f2s <= -f1 }
            while (lo < hi2) {
                int mid = (lo + hi2) >> 1;
                if (g_f2s[mid] <= tt) lo = mid + 1; else hi2 = mid;
            }
            g_p[row] = lo;
            g_c[row] = expf((ALPHA - 1.0f) * f1);
        }
    }
    gbar(gen);

    // ===== Phase G: combine + ELU ===========================================
    {
        const int d = gtid & 63;           // invariant: GSIZE % 64 == 0
        double toth = g_Phi[(N - 1) * D + d];
        double tosh = g_pshi[N - 1];
        for (int idx = gtid; idx < N * D; idx += GSIZE) {
            int row = idx >> 6;
            int   p = g_p[row];
            float c = g_c[row];
            double num = toth, den = tosh;
            if (p > 0) {
                num = num - g_Phi[(p - 1) * D + d] + (double)c * g_Plo[(p - 1) * D + d];
                den = den - g_pshi[p - 1] + (double)c * g_pslo[p - 1];
            }
            float v = __fdividef((float)num, (float)den);
            out[idx] = (v > 0.f) ? v : expm1f(v);
        }
    }
}

// ---------------- launch ----------------------------------------------------
extern "C" void kernel_launch(void* const* d_in, const int* in_sizes, int n_in,
                              void* d_out, int out_size) {
    const float* x  = (const float*)d_in[0];
    const float* Wt = (const float*)d_in[1];
    const float* a1 = (const float*)d_in[2];
    const float* b1 = (const float*)d_in[3];
    const float* a2 = (const float*)d_in[4];
    const float* b2 = (const float*)d_in[5];
    float* out = (float*)d_out;

    k_fused<<<NBLK, NTHR>>>(x, Wt, a1, b1, a2, b2, out);
}

// round 8
// speedup vs baseline: 1.2153x; 1.2008x over previous
#include <cuda_runtime.h>
#include <math.h>

#define N 8192
#define D 64
#define ALPHA 0.2f
#define NB 16384
#define SHIFT 18           // bucket = top 14 bits of order-flipped float key
#define NBLK 130
#define NTHR 1024
#define GSIZE (NBLK * NTHR)

// ---------------- scratch (device globals; no allocation allowed) -----------
__device__ float    g_h[N * D];        // projected features (2 MB)
__device__ float    g_hsT[D * N];      // h, sorted order, TRANSPOSED [d][k] (2 MB)
__device__ float    g_f1[N];
__device__ float    g_f2[N];
__device__ unsigned g_ukey[N];
__device__ int      g_hist[NB];
__device__ int      g_incl[NB];        // block-local inclusive scan of hist
__device__ int      g_btot[16];
__device__ int      g_start[NB + 1];
__device__ int      g_cursor[NB];
__device__ unsigned g_bkey[N];
__device__ int      g_bidx[N];
__device__ float    g_f2s[N];          // f2 sorted ascending
__device__ int      g_ord[N];          // sorted position -> original index
__device__ float    g_ehi[N];          // e^{f2s}
__device__ float    g_elo[N];          // e^{ALPHA*f2s}
__device__ int      g_p[N];            // per-row split point
__device__ float    g_c[N];            // per-row e^{(ALPHA-1) f1}
__device__ float    g_Shi[(N + 1) * D];// SUFFIX sums of e^{f2} h, [k][d]; Shi[N]=0
__device__ float    g_Plo[(N + 1) * D];// PREFIX sums of e^{a f2} h, shifted; Plo[0]=0
__device__ float    g_pshis[N + 1];    // scalar suffix of e^{f2};   [N]=0
__device__ float    g_pslos[N + 1];    // scalar prefix of e^{a f2}; [0]=0

// ---------------- software grid barrier -------------------------------------
__device__ unsigned g_bar_arrive = 0;
__device__ unsigned g_bar_gen    = 0;

__device__ __forceinline__ void gbar(unsigned& gen) {
    __syncthreads();
    if (threadIdx.x == 0) {
        __threadfence();
        unsigned my = gen;
        if (atomicAdd(&g_bar_arrive, 1) == NBLK - 1) {
            g_bar_arrive = 0;          // reset BEFORE release (ordered by fence)
            __threadfence();
            atomicAdd(&g_bar_gen, 1);
        } else {
            while (*(volatile unsigned*)&g_bar_gen == my) __nanosleep(32);
        }
        __threadfence();
        gen = my + 1;
    }
    __syncthreads();
}

// ---------------- the single persistent kernel ------------------------------
__global__ void __launch_bounds__(NTHR, 1) k_fused(
    const float* __restrict__ x,  const float* __restrict__ Wt,
    const float* __restrict__ a1, const float* __restrict__ b1,
    const float* __restrict__ a2, const float* __restrict__ b2,
    float* __restrict__ out)
{
    __shared__ float  sWt[D * D];      // 16 KB
    __shared__ float  sx[16 * D];      // 4 KB
    __shared__ float  sa1[D], sa2[D];
    __shared__ float  sred1[32], sred2[32];
    __shared__ int    sint[32];
    __shared__ double sdbl[32];

    const int t    = threadIdx.x;
    const int b    = blockIdx.x;
    const int gtid = b * NTHR + t;
    const int lane = t & 31, warp = t >> 5;
    unsigned gen = *(volatile unsigned*)&g_bar_gen;   // per-launch snapshot

    // ===== Phase A: projection h = x*Wt, scores f1/f2, key + histogram ======
    if (b < 128) {
        for (int i = t; i < D * D; i += NTHR) sWt[i] = Wt[i];
        if (t < D) { sa1[t] = a1[t]; sa2[t] = a2[t]; }
        const int r = t >> 6;          // 0..15 local row
        const int d = t & 63;
        for (int chunk = 0; chunk < 4; chunk++) {
            const int row0 = b * 64 + chunk * 16;
            __syncthreads();           // protect sx reuse (and sWt on chunk 0)
            for (int i = t; i < 16 * D; i += NTHR) sx[i] = x[row0 * D + i];
            __syncthreads();
            float h = 0.f;
            #pragma unroll
            for (int k = 0; k < D; k += 4) {
                float4 xv = *(const float4*)&sx[r * D + k];
                h = fmaf(xv.x, sWt[(k + 0) * D + d], h);
                h = fmaf(xv.y, sWt[(k + 1) * D + d], h);
                h = fmaf(xv.z, sWt[(k + 2) * D + d], h);
                h = fmaf(xv.w, sWt[(k + 3) * D + d], h);
            }
            g_h[(row0 + r) * D + d] = h;

            float p1 = h * sa1[d];
            float p2 = h * sa2[d];
            #pragma unroll
            for (int off = 16; off > 0; off >>= 1) {
                p1 += __shfl_down_sync(0xffffffffu, p1, off);
                p2 += __shfl_down_sync(0xffffffffu, p2, off);
            }
            if (lane == 0) { sred1[warp] = p1; sred2[warp] = p2; }
            __syncthreads();
            if (t < 16) {
                float f1  = sred1[2 * t] + sred1[2 * t + 1] + b1[0];
                float f2v = sred2[2 * t] + sred2[2 * t + 1] + b2[0];
                int row = row0 + t;
                g_f1[row] = f1;
                g_f2[row] = f2v;
                unsigned u = __float_as_uint(f2v);
                u ^= (u >> 31) ? 0xFFFFFFFFu : 0x80000000u;
                g_ukey[row] = u;
                atomicAdd(&g_hist[u >> SHIFT], 1);
            }
        }
    }
    gbar(gen);

    // ===== Phase B1: per-block inclusive scan of histogram (16 blocks) ======
    if (b < 16) {
        int i = b * NTHR + t;
        int v = g_hist[i];
        int s = v;
        #pragma unroll
        for (int off = 1; off < 32; off <<= 1) {
            int o = __shfl_up_sync(0xffffffffu, s, off);
            if (lane >= off) s += o;
        }
        if (lane == 31) sint[warp] = s;
        __syncthreads();
        if (t < 32) {
            int w2 = sint[t];
            #pragma unroll
            for (int off = 1; off < 32; off <<= 1) {
                int o = __shfl_up_sync(0xffffffffu, w2, off);
                if (t >= off) w2 += o;
            }
            sint[t] = w2;
        }
        __syncthreads();
        int incl = s + (warp ? sint[warp - 1] : 0);
        g_incl[i] = incl;
        if (t == NTHR - 1) g_btot[b] = incl;
    }
    gbar(gen);

    // ===== Phase B3: global offsets -> start/cursor =========================
    if (b < 16) {
        int off = 0;
        #pragma unroll
        for (int j = 0; j < 16; j++) if (j < b) off += g_btot[j];
        int i = b * NTHR + t;
        int excl = off + g_incl[i] - g_hist[i];
        g_start[i]  = excl;
        g_cursor[i] = excl;
    }
    if (b == 0 && t == 0) g_start[NB] = N;
    gbar(gen);

    // ===== Phase C: scatter into buckets; spare threads re-zero histogram ===
    if (gtid < N) {
        unsigned u = g_ukey[gtid];
        int pos = atomicAdd(&g_cursor[u >> SHIFT], 1);
        g_bkey[pos] = u;
        g_bidx[pos] = gtid;
    } else if (gtid - N < NB) {
        g_hist[gtid - N] = 0;
    }
    gbar(gen);

    // ===== Phase D: rank within bucket (16 threads/element) =================
    {
        int el  = gtid >> 4;           // 0..8319
        int seg = gtid & 15;
        if (el < N) {
            unsigned u = g_bkey[el];
            int i  = g_bidx[el];
            int bk = u >> SHIFT;
            int st = g_start[bk], en = g_start[bk + 1];
            int rank = 0;
            for (int j = st + seg; j < en; j += 16) {
                unsigned kj = g_bkey[j];
                rank += (kj < u) || (kj == u && g_bidx[j] < i);
            }
            #pragma unroll
            for (int off = 8; off > 0; off >>= 1)
                rank += __shfl_down_sync(0xffffffffu, rank, off, 16);
            if (seg == 0) {
                rank += st;
                float f2v = g_f2[i];
                g_f2s[rank] = f2v;
                g_ord[rank] = i;
                g_ehi[rank] = expf(f2v);
                g_elo[rank] = expf(ALPHA * f2v);
            }
        }
    }
    gbar(gen);

    // ===== Phase D2: transpose h into sorted order, all blocks ==============
    for (int idx = gtid; idx < N * D; idx += GSIZE) {
        int d = idx >> 13;
        int k = idx & (N - 1);
        g_hsT[idx] = g_h[g_ord[k] * D + d];
    }
    gbar(gen);

    // ===== Phase E: 130 directional fp64-accum scans, fp32 store + psearch ==
    // hi blocks (b<64 dims, b==128 scalar): SUFFIX scan  -> g_Shi / g_pshis
    // lo blocks (64..127 dims, b==129 scalar): PREFIX scan -> g_Plo / g_pslos
    if (b < 130) {
        bool scalar = (b >= 128);
        bool hi = (b < 64) || (b == 128);
        int dim = scalar ? 0 : (hi ? b : b - 64);
        const float* e    = hi ? g_ehi : g_elo;
        const float* hrow = g_hsT + (size_t)dim * N;

        int k0 = t * 8;
        double v[8];
        double run = 0.0;
        if (hi) {                      // local SUFFIX within chunk (j desc)
            #pragma unroll
            for (int j = 7; j >= 0; j--) {
                double val = (double)e[k0 + j];
                if (!scalar) val *= (double)hrow[k0 + j];
                run += val;
                v[j] = run;            // = sum over [k0+j, k0+8)
            }
        } else {                       // local PREFIX within chunk (j asc)
            #pragma unroll
            for (int j = 0; j < 8; j++) {
                double val = (double)e[k0 + j];
                if (!scalar) val *= (double)hrow[k0 + j];
                run += val;
                v[j] = run;            // = sum over [k0, k0+j]
            }
        }
        double w = run;
        if (hi) {                      // reverse inclusive scan across lanes
            #pragma unroll
            for (int off = 1; off < 32; off <<= 1) {
                double o = __shfl_down_sync(0xffffffffu, w, off);
                if (lane + off < 32) w += o;
            }
            if (lane == 0) sdbl[warp] = w;          // full warp sum
            __syncthreads();
            if (t < 32) {
                double x2 = sdbl[t];
                #pragma unroll
                for (int off = 1; off < 32; off <<= 1) {
                    double o = __shfl_down_sync(0xffffffffu, x2, off);
                    if (t + off < 32) x2 += o;
                }
                sdbl[t] = x2;                        // = sum over warps >= t
            }
            __syncthreads();
            double base = (w - run) + (warp < 31 ? sdbl[warp + 1] : 0.0);
            if (scalar) {
                #pragma unroll
                for (int j = 0; j < 8; j++) g_pshis[k0 + j] = (float)(base + v[j]);
                if (t == 0) g_pshis[N] = 0.f;
            } else {
                #pragma unroll
                for (int j = 0; j < 8; j++) g_Shi[(k0 + j) * D + dim] = (float)(base + v[j]);
                if (t == 0) g_Shi[N * D + dim] = 0.f;
            }
        } else {                       // forward inclusive scan across lanes
            #pragma unroll
            for (int off = 1; off < 32; off <<= 1) {
                double o = __shfl_up_sync(0xffffffffu, w, off);
                if (lane >= off) w += o;
            }
            if (lane == 31) sdbl[warp] = w;
            __syncthreads();
            if (t < 32) {
                double x2 = sdbl[t];
                #pragma unroll
                for (int off = 1; off < 32; off <<= 1) {
                    double o = __shfl_up_sync(0xffffffffu, x2, off);
                    if (t >= off) x2 += o;
                }
                sdbl[t] = x2;
            }
            __syncthreads();
            double base = (w - run) + (warp ? sdbl[warp - 1] : 0.0);
            // shifted storage: Plo[k+1] = prefix including element k; Plo[0]=0
            if (scalar) {
                #pragma unroll
                for (int j = 0; j < 8; j++) g_pslos[k0 + j + 1] = (float)(base + v[j]);
                if (t == 0) g_pslos[0] = 0.f;
            } else {
                #pragma unroll
                for (int j = 0; j < 8; j++) g_Plo[(k0 + j + 1) * D + dim] = (float)(base + v[j]);
                if (t == 0) g_Plo[dim] = 0.f;
            }
        }

        // per-row binary search (idle-lane work, independent of scan stores)
        if (t < 64 && b < 128) {
            int row = b * 64 + t;
            float f1 = g_f1[row];
            float tt = -f1;
            int lo = 0, hi2 = N;           // p = #{ f2s <= -f1 }
            while (lo < hi2) {
                int mid = (lo + hi2) >> 1;
                if (g_f2s[mid] <= tt) lo = mid + 1; else hi2 = mid;
            }
            g_p[row] = lo;
            g_c[row] = expf((ALPHA - 1.0f) * f1);
        }
    }
    gbar(gen);

    // ===== Phase G: branchless fp32 combine + ELU ===========================
    {
        const int d = gtid & 63;           // invariant: GSIZE % 64 == 0
        for (int idx = gtid; idx < N * D; idx += GSIZE) {
            int row = idx >> 6;
            int   p = g_p[row];
            float c = g_c[row];
            float num = g_Shi[p * D + d] + c * g_Plo[p * D + d];
            float den = g_pshis[p]       + c * g_pslos[p];
            float v = __fdividef(num, den);
            out[idx] = (v > 0.f) ? v : expm1f(v);
        }
    }
}

// ---------------- launch ----------------------------------------------------
extern "C" void kernel_launch(void* const* d_in, const int* in_sizes, int n_in,
                              void* d_out, int out_size) {
    const float* x  = (const float*)d_in[0];
    const float* Wt = (const float*)d_in[1];
    const float* a1 = (const float*)d_in[2];
    const float* b1 = (const float*)d_in[3];
    const float* a2 = (const float*)d_in[4];
    const float* b2 = (const float*)d_in[5];
    float* out = (float*)d_out;

    k_fused<<<NBLK, NTHR>>>(x, Wt, a1, b1, a2, b2, out);
}

// round 9
// speedup vs baseline: 1.2649x; 1.0408x over previous
#include <cuda_runtime.h>
#include <math.h>

#define N 8192
#define D 64
#define ALPHA 0.2f
#define NB 16384
#define SHIFT 18           // bucket = top 14 bits of order-flipped float key
#define NBLK 130
#define NTHR 1024
#define GSIZE (NBLK * NTHR)

// ---------------- scratch (device globals; no allocation allowed) -----------
__device__ float    g_h[N * D];        // projected features (2 MB)
__device__ float    g_hsT[D * N];      // h, sorted order, TRANSPOSED [d][k] (2 MB)
__device__ float    g_f1[N];
__device__ float    g_f2[N];
__device__ unsigned g_ukey[N];
__device__ int      g_hist[NB];
__device__ int      g_incl[NB];        // block-local inclusive scan of hist
__device__ int      g_btot[16];
__device__ int      g_start[NB + 1];
__device__ int      g_cursor[NB];
__device__ unsigned g_bkey[N];
__device__ int      g_bidx[N];
__device__ float    g_f2s[N];          // f2 sorted ascending
__device__ int      g_ord[N];          // sorted position -> original index
__device__ float    g_ehi[N];          // e^{f2s}
__device__ float    g_elo[N];          // e^{ALPHA*f2s}
__device__ int      g_p[N];            // per-row split point
__device__ float    g_c[N];            // per-row e^{(ALPHA-1) f1}
__device__ float    g_Shi[(N + 1) * D];// SUFFIX sums of e^{f2} h, [k][d]; Shi[N]=0
__device__ float    g_Plo[(N + 1) * D];// PREFIX sums of e^{a f2} h, shifted; Plo[0]=0
__device__ float    g_pshis[N + 1];    // scalar suffix of e^{f2};   [N]=0
__device__ float    g_pslos[N + 1];    // scalar prefix of e^{a f2}; [0]=0

// ---------------- software grid barrier -------------------------------------
__device__ unsigned g_bar_arrive = 0;
__device__ unsigned g_bar_gen    = 0;

__device__ __forceinline__ void gbar(unsigned& gen) {
    __syncthreads();
    if (threadIdx.x == 0) {
        __threadfence();
        unsigned my = gen;
        if (atomicAdd(&g_bar_arrive, 1) == NBLK - 1) {
            g_bar_arrive = 0;          // reset BEFORE release (ordered by fence)
            __threadfence();
            atomicAdd(&g_bar_gen, 1);
        } else {
            while (*(volatile unsigned*)&g_bar_gen == my) __nanosleep(32);
        }
        __threadfence();
        gen = my + 1;
    }
    __syncthreads();
}

// ---------------- the single persistent kernel ------------------------------
__global__ void __launch_bounds__(NTHR, 1) k_fused(
    const float* __restrict__ x,  const float* __restrict__ Wt,
    const float* __restrict__ a1, const float* __restrict__ b1,
    const float* __restrict__ a2, const float* __restrict__ b2,
    float* __restrict__ out)
{
    __shared__ float  sWt[D * D];      // 16 KB
    __shared__ float  sx[D * D];       // 16 KB (64 rows of x)
    __shared__ float  sa1[D], sa2[D];
    __shared__ int    sint[32];
    __shared__ double sdbl[32];

    const int t    = threadIdx.x;
    const int b    = blockIdx.x;
    const int gtid = b * NTHR + t;
    const int lane = t & 31, warp = t >> 5;
    unsigned gen = *(volatile unsigned*)&g_bar_gen;   // per-launch snapshot

    // ===== Phase A: projection h = x*Wt, scores f1/f2, key + histogram ======
    // thread = (row t>>4, d-quad (t&15)*4): 4 outputs in registers,
    // 1 broadcast LDS + 1 LDS.128 per 4 FMA, single __syncthreads.
    if (b < 128) {
        for (int i = t; i < D * D; i += NTHR) sWt[i] = Wt[i];
        for (int i = t; i < D * D; i += NTHR) sx[i]  = x[b * (D * D) + i];
        if (t < D) { sa1[t] = a1[t]; sa2[t] = a2[t]; }
        __syncthreads();

        const int r   = t >> 4;                 // 0..63 local row
        const int dq  = (t & 15) * 4;           // d-quad base
        const int row = b * 64 + r;
        const float* xr = sx + r * D;

        float acc0 = 0.f, acc1 = 0.f, acc2 = 0.f, acc3 = 0.f;
        #pragma unroll 16
        for (int k = 0; k < D; k++) {
            float  xv = xr[k];
            float4 wv = *(const float4*)&sWt[k * D + dq];
            acc0 = fmaf(xv, wv.x, acc0);
            acc1 = fmaf(xv, wv.y, acc1);
            acc2 = fmaf(xv, wv.z, acc2);
            acc3 = fmaf(xv, wv.w, acc3);
        }
        *(float4*)&g_h[row * D + dq] = make_float4(acc0, acc1, acc2, acc3);

        float4 a1v = *(const float4*)&sa1[dq];
        float4 a2v = *(const float4*)&sa2[dq];
        float q1 = acc0 * a1v.x + acc1 * a1v.y + acc2 * a1v.z + acc3 * a1v.w;
        float q2 = acc0 * a2v.x + acc1 * a2v.y + acc2 * a2v.z + acc3 * a2v.w;
        #pragma unroll
        for (int off = 8; off > 0; off >>= 1) {
            q1 += __shfl_down_sync(0xffffffffu, q1, off, 16);
            q2 += __shfl_down_sync(0xffffffffu, q2, off, 16);
        }
        if ((t & 15) == 0) {
            float f1v = q1 + b1[0];
            float f2v = q2 + b2[0];
            g_f1[row] = f1v;
            g_f2[row] = f2v;
            unsigned u = __float_as_uint(f2v);
            u ^= (u >> 31) ? 0xFFFFFFFFu : 0x80000000u;
            g_ukey[row] = u;
            atomicAdd(&g_hist[u >> SHIFT], 1);
        }
    }
    gbar(gen);

    // ===== Phase B1: per-block inclusive scan of histogram (16 blocks) ======
    if (b < 16) {
        int i = b * NTHR + t;
        int v = g_hist[i];
        int s = v;
        #pragma unroll
        for (int off = 1; off < 32; off <<= 1) {
            int o = __shfl_up_sync(0xffffffffu, s, off);
            if (lane >= off) s += o;
        }
        if (lane == 31) sint[warp] = s;
        __syncthreads();
        if (t < 32) {
            int w2 = sint[t];
            #pragma unroll
            for (int off = 1; off < 32; off <<= 1) {
                int o = __shfl_up_sync(0xffffffffu, w2, off);
                if (t >= off) w2 += o;
            }
            sint[t] = w2;
        }
        __syncthreads();
        int incl = s + (warp ? sint[warp - 1] : 0);
        g_incl[i] = incl;
        if (t == NTHR - 1) g_btot[b] = incl;
    }
    gbar(gen);

    // ===== Phase B3: global offsets -> start/cursor =========================
    if (b < 16) {
        int off = 0;
        #pragma unroll
        for (int j = 0; j < 16; j++) if (j < b) off += g_btot[j];
        int i = b * NTHR + t;
        int excl = off + g_incl[i] - g_hist[i];
        g_start[i]  = excl;
        g_cursor[i] = excl;
    }
    if (b == 0 && t == 0) g_start[NB] = N;
    gbar(gen);

    // ===== Phase C: scatter into buckets; spare threads re-zero histogram ===
    if (gtid < N) {
        unsigned u = g_ukey[gtid];
        int pos = atomicAdd(&g_cursor[u >> SHIFT], 1);
        g_bkey[pos] = u;
        g_bidx[pos] = gtid;
    } else if (gtid - N < NB) {
        g_hist[gtid - N] = 0;
    }
    gbar(gen);

    // ===== Phase D: rank within bucket (16 threads/element) =================
    {
        int el  = gtid >> 4;           // 0..8319
        int seg = gtid & 15;
        if (el < N) {
            unsigned u = g_bkey[el];
            int i  = g_bidx[el];
            int bk = u >> SHIFT;
            int st = g_start[bk], en = g_start[bk + 1];
            int rank = 0;
            for (int j = st + seg; j < en; j += 16) {
                unsigned kj = g_bkey[j];
                rank += (kj < u) || (kj == u && g_bidx[j] < i);
            }
            #pragma unroll
            for (int off = 8; off > 0; off >>= 1)
                rank += __shfl_down_sync(0xffffffffu, rank, off, 16);
            if (seg == 0) {
                rank += st;
                float f2v = g_f2[i];
                g_f2s[rank] = f2v;
                g_ord[rank] = i;
                g_ehi[rank] = expf(f2v);
                g_elo[rank] = expf(ALPHA * f2v);
            }
        }
    }
    gbar(gen);

    // ===== Phase D2: transpose h into sorted order, all blocks ==============
    for (int idx = gtid; idx < N * D; idx += GSIZE) {
        int d = idx >> 13;
        int k = idx & (N - 1);
        g_hsT[idx] = g_h[g_ord[k] * D + d];
    }
    gbar(gen);

    // ===== Phase E: 130 directional fp64-accum scans, fp32 store + psearch ==
    // hi blocks (b<64 dims, b==128 scalar): SUFFIX scan  -> g_Shi / g_pshis
    // lo blocks (64..127 dims, b==129 scalar): PREFIX scan -> g_Plo / g_pslos
    if (b < 130) {
        bool scalar = (b >= 128);
        bool hi = (b < 64) || (b == 128);
        int dim = scalar ? 0 : (hi ? b : b - 64);
        const float* e    = hi ? g_ehi : g_elo;
        const float* hrow = g_hsT + (size_t)dim * N;

        int k0 = t * 8;
        double v[8];
        double run = 0.0;
        if (hi) {                      // local SUFFIX within chunk (j desc)
            #pragma unroll
            for (int j = 7; j >= 0; j--) {
                double val = (double)e[k0 + j];
                if (!scalar) val *= (double)hrow[k0 + j];
                run += val;
                v[j] = run;            // = sum over [k0+j, k0+8)
            }
        } else {                       // local PREFIX within chunk (j asc)
            #pragma unroll
            for (int j = 0; j < 8; j++) {
                double val = (double)e[k0 + j];
                if (!scalar) val *= (double)hrow[k0 + j];
                run += val;
                v[j] = run;            // = sum over [k0, k0+j]
            }
        }
        double w = run;
        if (hi) {                      // reverse inclusive scan across lanes
            #pragma unroll
            for (int off = 1; off < 32; off <<= 1) {
                double o = __shfl_down_sync(0xffffffffu, w, off);
                if (lane + off < 32) w += o;
            }
            if (lane == 0) sdbl[warp] = w;          // full warp sum
            __syncthreads();
            if (t < 32) {
                double x2 = sdbl[t];
                #pragma unroll
                for (int off = 1; off < 32; off <<= 1) {
                    double o = __shfl_down_sync(0xffffffffu, x2, off);
                    if (t + off < 32) x2 += o;
                }
                sdbl[t] = x2;                        // = sum over warps >= t
            }
            __syncthreads();
            double base = (w - run) + (warp < 31 ? sdbl[warp + 1] : 0.0);
            if (scalar) {
                #pragma unroll
                for (int j = 0; j < 8; j++) g_pshis[k0 + j] = (float)(base + v[j]);
                if (t == 0) g_pshis[N] = 0.f;
            } else {
                #pragma unroll
                for (int j = 0; j < 8; j++) g_Shi[(k0 + j) * D + dim] = (float)(base + v[j]);
                if (t == 0) g_Shi[N * D + dim] = 0.f;
            }
        } else {                       // forward inclusive scan across lanes
            #pragma unroll
            for (int off = 1; off < 32; off <<= 1) {
                double o = __shfl_up_sync(0xffffffffu, w, off);
                if (lane >= off) w += o;
            }
            if (lane == 31) sdbl[warp] = w;
            __syncthreads();
            if (t < 32) {
                double x2 = sdbl[t];
                #pragma unroll
                for (int off = 1; off < 32; off <<= 1) {
                    double o = __shfl_up_sync(0xffffffffu, x2, off);
                    if (t >= off) x2 += o;
                }
                sdbl[t] = x2;
            }
            __syncthreads();
            double base = (w - run) + (warp ? sdbl[warp - 1] : 0.0);
            // shifted storage: Plo[k+1] = prefix including element k; Plo[0]=0
            if (scalar) {
                #pragma unroll
                for (int j = 0; j < 8; j++) g_pslos[k0 + j + 1] = (float)(base + v[j]);
                if (t == 0) g_pslos[0] = 0.f;
            } else {
                #pragma unroll
                for (int j = 0; j < 8; j++) g_Plo[(k0 + j + 1) * D + dim] = (float)(base + v[j]);
                if (t == 0) g_Plo[dim] = 0.f;
            }
        }

        // per-row binary search (idle-lane work, independent of scan stores)
        if (t < 64 && b < 128) {
            int row = b * 64 + t;
            float f1 = g_f1[row];
            float tt = -f1;
            int lo = 0, hi2 = N;           // p = #{ f2s <= -f1 }
            while (lo < hi2) {
                int mid = (lo + hi2) >> 1;
                if (g_f2s[mid] <= tt) lo = mid + 1; else hi2 = mid;
            }
            g_p[row] = lo;
            g_c[row] = expf((ALPHA - 1.0f) * f1);
        }
    }
    gbar(gen);

    // ===== Phase G: branchless fp32 combine + ELU ===========================
    {
        const int d = gtid & 63;           // invariant: GSIZE % 64 == 0
        for (int idx = gtid; idx < N * D; idx += GSIZE) {
            int row = idx >> 6;
            int   p = g_p[row];
            float c = g_c[row];
            float num = g_Shi[p * D + d] + c * g_Plo[p * D + d];
            float den = g_pshis[p]       + c * g_pslos[p];
            float v = __fdividef(num, den);
            out[idx] = (v > 0.f) ? v : expm1f(v);
        }
    }
}

// ---------------- launch ----------------------------------------------------
extern "C" void kernel_launch(void* const* d_in, const int* in_sizes, int n_in,
                              void* d_out, int out_size) {
    const float* x  = (const float*)d_in[0];
    const float* Wt = (const float*)d_in[1];
    const float* a1 = (const float*)d_in[2];
    const float* b1 = (const float*)d_in[3];
    const float* a2 = (const float*)d_in[4];
    const float* b2 = (const float*)d_in[5];
    float* out = (float*)d_out;

    k_fused<<<NBLK, NTHR>>>(x, Wt, a1, b1, a2, b2, out);
}

// round 10
// speedup vs baseline: 1.3369x; 1.0569x over previous
#include <cuda_runtime.h>
#include <math.h>

#define N 8192
#define D 64
#define ALPHA 0.2f
#define NB 16384
#define SHIFT 18           // bucket = top 14 bits of order-flipped float key
#define NBLK 130
#define NTHR 1024
#define GSIZE (NBLK * NTHR)

// ---------------- scratch (device globals; no allocation allowed) -----------
__device__ float    g_h[N * D];        // projected features (2 MB)
__device__ float    g_hsT[D * N];      // h, sorted order, TRANSPOSED [d][k] (2 MB)
__device__ float    g_f1[N];
__device__ float    g_f2[N];
__device__ unsigned g_ukey[N];
__device__ int      g_hist[NB];
__device__ int      g_incl[NB];        // block-local inclusive scan of hist
__device__ int      g_btot[16];
__device__ int      g_start[NB + 1];
__device__ int      g_cursor[NB];
__device__ unsigned g_bkey[N];
__device__ int      g_bidx[N];
__device__ float    g_f2s[N];          // f2 sorted ascending
__device__ int      g_ord[N];          // sorted position -> original index
__device__ float    g_ehi[N];          // e^{f2s}
__device__ float    g_elo[N];          // e^{ALPHA*f2s}
__device__ int      g_p[N];            // per-row split point
__device__ float    g_c[N];            // per-row e^{(ALPHA-1) f1}
__device__ float    g_SThi[D * N];     // suffix sums, transposed [d][k] (2 MB)
__device__ float    g_STlo[D * N];     // prefix sums, transposed [d][k] (2 MB)
__device__ float    g_Shi[(N + 1) * D];// SUFFIX sums [k][d]; row N = 0
__device__ float    g_Plo[(N + 1) * D];// PREFIX sums shifted [k][d]; row 0 = 0
__device__ float    g_pshis[N + 1];    // scalar suffix of e^{f2};   [N]=0
__device__ float    g_pslos[N + 1];    // scalar prefix of e^{a f2}; [0]=0

// ---------------- software grid barrier -------------------------------------
__device__ unsigned g_bar_arrive = 0;
__device__ unsigned g_bar_gen    = 0;

__device__ __forceinline__ void gbar(unsigned& gen) {
    __syncthreads();
    if (threadIdx.x == 0) {
        __threadfence();
        unsigned my = gen;
        if (atomicAdd(&g_bar_arrive, 1) == NBLK - 1) {
            g_bar_arrive = 0;          // reset BEFORE release (ordered by fence)
            __threadfence();
            atomicAdd(&g_bar_gen, 1);
        } else {
            while (*(volatile unsigned*)&g_bar_gen == my) __nanosleep(32);
        }
        __threadfence();
        gen = my + 1;
    }
    __syncthreads();
}

// ---------------- the single persistent kernel ------------------------------
__global__ void __launch_bounds__(NTHR, 1) k_fused(
    const float* __restrict__ x,  const float* __restrict__ Wt,
    const float* __restrict__ a1, const float* __restrict__ b1,
    const float* __restrict__ a2, const float* __restrict__ b2,
    float* __restrict__ out)
{
    __shared__ __align__(16) char sbuf[33280];   // A: sWt|sx|sa1|sa2 ; D2/F: 64x65 tile
    __shared__ int    sord[64];
    __shared__ int    sint[32];
    __shared__ double sdbl[32];

    const int t    = threadIdx.x;
    const int b    = blockIdx.x;
    const int gtid = b * NTHR + t;
    const int lane = t & 31, warp = t >> 5;
    unsigned gen = *(volatile unsigned*)&g_bar_gen;   // per-launch snapshot

    // ===== Phase A: projection h = x*Wt, scores f1/f2, key + histogram ======
    if (b < 128) {
        float* sWt = (float*)sbuf;                 // 16 KB
        float* sx  = (float*)(sbuf + 16384);       // 16 KB
        float* sa1 = (float*)(sbuf + 32768);
        float* sa2 = (float*)(sbuf + 33024);
        for (int i = t; i < D * D; i += NTHR) sWt[i] = Wt[i];
        for (int i = t; i < D * D; i += NTHR) sx[i]  = x[b * (D * D) + i];
        if (t < D) { sa1[t] = a1[t]; sa2[t] = a2[t]; }
        __syncthreads();

        const int r   = t >> 4;                 // 0..63 local row
        const int dq  = (t & 15) * 4;           // d-quad base
        const int row = b * 64 + r;
        const float* xr = sx + r * D;

        float acc0 = 0.f, acc1 = 0.f, acc2 = 0.f, acc3 = 0.f;
        #pragma unroll 16
        for (int k = 0; k < D; k++) {
            float  xv = xr[k];
            float4 wv = *(const float4*)&sWt[k * D + dq];
            acc0 = fmaf(xv, wv.x, acc0);
            acc1 = fmaf(xv, wv.y, acc1);
            acc2 = fmaf(xv, wv.z, acc2);
            acc3 = fmaf(xv, wv.w, acc3);
        }
        *(float4*)&g_h[row * D + dq] = make_float4(acc0, acc1, acc2, acc3);

        float4 a1v = *(const float4*)&sa1[dq];
        float4 a2v = *(const float4*)&sa2[dq];
        float q1 = acc0 * a1v.x + acc1 * a1v.y + acc2 * a1v.z + acc3 * a1v.w;
        float q2 = acc0 * a2v.x + acc1 * a2v.y + acc2 * a2v.z + acc3 * a2v.w;
        #pragma unroll
        for (int off = 8; off > 0; off >>= 1) {
            q1 += __shfl_down_sync(0xffffffffu, q1, off, 16);
            q2 += __shfl_down_sync(0xffffffffu, q2, off, 16);
        }
        if ((t & 15) == 0) {
            float f1v = q1 + b1[0];
            float f2v = q2 + b2[0];
            g_f1[row] = f1v;
            g_f2[row] = f2v;
            unsigned u = __float_as_uint(f2v);
            u ^= (u >> 31) ? 0xFFFFFFFFu : 0x80000000u;
            g_ukey[row] = u;
            atomicAdd(&g_hist[u >> SHIFT], 1);
        }
    }
    gbar(gen);

    // ===== Phase B1: per-block inclusive scan of histogram (16 blocks) ======
    if (b < 16) {
        int i = b * NTHR + t;
        int v = g_hist[i];
        int s = v;
        #pragma unroll
        for (int off = 1; off < 32; off <<= 1) {
            int o = __shfl_up_sync(0xffffffffu, s, off);
            if (lane >= off) s += o;
        }
        if (lane == 31) sint[warp] = s;
        __syncthreads();
        if (t < 32) {
            int w2 = sint[t];
            #pragma unroll
            for (int off = 1; off < 32; off <<= 1) {
                int o = __shfl_up_sync(0xffffffffu, w2, off);
                if (t >= off) w2 += o;
            }
            sint[t] = w2;
        }
        __syncthreads();
        int incl = s + (warp ? sint[warp - 1] : 0);
        g_incl[i] = incl;
        if (t == NTHR - 1) g_btot[b] = incl;
    }
    gbar(gen);

    // ===== Phase B3: global offsets -> start/cursor =========================
    if (b < 16) {
        int off = 0;
        #pragma unroll
        for (int j = 0; j < 16; j++) if (j < b) off += g_btot[j];
        int i = b * NTHR + t;
        int excl = off + g_incl[i] - g_hist[i];
        g_start[i]  = excl;
        g_cursor[i] = excl;
    }
    if (b == 0 && t == 0) g_start[NB] = N;
    gbar(gen);

    // ===== Phase C: scatter (128 blocks x 64) + re-zero histogram ===========
    if (b < 128) {
        if (t < 64) {
            int i = b * 64 + t;
            unsigned u = g_ukey[i];
            int pos = atomicAdd(&g_cursor[u >> SHIFT], 1);
            g_bkey[pos] = u;
            g_bidx[pos] = i;
        } else if (t < 192) {
            g_hist[b * 128 + (t - 64)] = 0;
        }
    }
    gbar(gen);

    // ===== Phase D: rank within bucket (16 threads/element) =================
    {
        int el  = gtid >> 4;           // 0..8319
        int seg = gtid & 15;
        if (el < N) {
            unsigned u = g_bkey[el];
            int i  = g_bidx[el];
            int bk = u >> SHIFT;
            int st = g_start[bk], en = g_start[bk + 1];
            int rank = 0;
            for (int j = st + seg; j < en; j += 16) {
                unsigned kj = g_bkey[j];
                rank += (kj < u) || (kj == u && g_bidx[j] < i);
            }
            #pragma unroll
            for (int off = 8; off > 0; off >>= 1)
                rank += __shfl_down_sync(0xffffffffu, rank, off, 16);
            if (seg == 0) {
                rank += st;
                float f2v = g_f2[i];
                g_f2s[rank] = f2v;
                g_ord[rank] = i;
                g_ehi[rank] = expf(f2v);
                g_elo[rank] = expf(ALPHA * f2v);
            }
        }
    }
    gbar(gen);

    // ===== Phase D2: smem-tiled permuted transpose h -> g_hsT[d][k] =========
    if (b < 128) {
        float* tile = (float*)sbuf;                // [64][65]
        const int k0 = b * 64;
        if (t < 64) sord[t] = g_ord[k0 + t];
        __syncthreads();
        {
            int kk = t >> 4, l4 = (t & 15) * 4;    // coalesced-ish row load
            float4 hv = *(const float4*)&g_h[sord[kk] * D + l4];
            tile[kk * 65 + l4 + 0] = hv.x;
            tile[kk * 65 + l4 + 1] = hv.y;
            tile[kk * 65 + l4 + 2] = hv.z;
            tile[kk * 65 + l4 + 3] = hv.w;
        }
        __syncthreads();
        {
            int d = t >> 4, kq = (t & 15) * 4;     // coalesced write along k
            float4 ov = make_float4(tile[(kq + 0) * 65 + d],
                                    tile[(kq + 1) * 65 + d],
                                    tile[(kq + 2) * 65 + d],
                                    tile[(kq + 3) * 65 + d]);
            *(float4*)&g_hsT[d * N + k0 + kq] = ov;
        }
    }
    gbar(gen);

    // ===== Phase E: 130 directional fp64-accum scans -> TRANSPOSED fp32 =====
    // hi blocks (b<64 dims, b==128 scalar): SUFFIX -> g_SThi / g_pshis
    // lo blocks (64..127, b==129 scalar):  PREFIX -> g_STlo / g_pslos
    if (b < 130) {
        bool scalar = (b >= 128);
        bool hi = (b < 64) || (b == 128);
        int dim = scalar ? 0 : (hi ? b : b - 64);
        const float* e    = hi ? g_ehi : g_elo;
        const float* hrow = g_hsT + (size_t)dim * N;

        int k0 = t * 8;
        double v[8];
        double run = 0.0;
        if (hi) {                      // local SUFFIX within chunk (j desc)
            #pragma unroll
            for (int j = 7; j >= 0; j--) {
                double val = (double)e[k0 + j];
                if (!scalar) val *= (double)hrow[k0 + j];
                run += val;
                v[j] = run;
            }
        } else {                       // local PREFIX within chunk (j asc)
            #pragma unroll
            for (int j = 0; j < 8; j++) {
                double val = (double)e[k0 + j];
                if (!scalar) val *= (double)hrow[k0 + j];
                run += val;
                v[j] = run;
            }
        }
        double w = run;
        if (hi) {                      // reverse inclusive scan across lanes
            #pragma unroll
            for (int off = 1; off < 32; off <<= 1) {
                double o = __shfl_down_sync(0xffffffffu, w, off);
                if (lane + off < 32) w += o;
            }
            if (lane == 0) sdbl[warp] = w;
            __syncthreads();
            if (t < 32) {
                double x2 = sdbl[t];
                #pragma unroll
                for (int off = 1; off < 32; off <<= 1) {
                    double o = __shfl_down_sync(0xffffffffu, x2, off);
                    if (t + off < 32) x2 += o;
                }
                sdbl[t] = x2;
            }
            __syncthreads();
            double base = (w - run) + (warp < 31 ? sdbl[warp + 1] : 0.0);
            if (scalar) {
                #pragma unroll
                for (int j = 0; j < 8; j++) g_pshis[k0 + j] = (float)(base + v[j]);
                if (t == 0) g_pshis[N] = 0.f;
            } else {
                float4 s0 = make_float4((float)(base + v[0]), (float)(base + v[1]),
                                        (float)(base + v[2]), (float)(base + v[3]));
                float4 s1 = make_float4((float)(base + v[4]), (float)(base + v[5]),
                                        (float)(base + v[6]), (float)(base + v[7]));
                *(float4*)&g_SThi[(size_t)dim * N + k0]     = s0;
                *(float4*)&g_SThi[(size_t)dim * N + k0 + 4] = s1;
            }
        } else {                       // forward inclusive scan across lanes
            #pragma unroll
            for (int off = 1; off < 32; off <<= 1) {
                double o = __shfl_up_sync(0xffffffffu, w, off);
                if (lane >= off) w += o;
            }
            if (lane == 31) sdbl[warp] = w;
            __syncthreads();
            if (t < 32) {
                double x2 = sdbl[t];
                #pragma unroll
                for (int off = 1; off < 32; off <<= 1) {
                    double o = __shfl_up_sync(0xffffffffu, x2, off);
                    if (t >= off) x2 += o;
                }
                sdbl[t] = x2;
            }
            __syncthreads();
            double base = (w - run) + (warp ? sdbl[warp - 1] : 0.0);
            if (scalar) {              // shifted: pslos[k+1] = incl prefix
                #pragma unroll
                for (int j = 0; j < 8; j++) g_pslos[k0 + j + 1] = (float)(base + v[j]);
                if (t == 0) g_pslos[0] = 0.f;
            } else {                   // unshifted transposed; shift applied in F
                float4 s0 = make_float4((float)(base + v[0]), (float)(base + v[1]),
                                        (float)(base + v[2]), (float)(base + v[3]));
                float4 s1 = make_float4((float)(base + v[4]), (float)(base + v[5]),
                                        (float)(base + v[6]), (float)(base + v[7]));
                *(float4*)&g_STlo[(size_t)dim * N + k0]     = s0;
                *(float4*)&g_STlo[(size_t)dim * N + k0 + 4] = s1;
            }
        }

        // per-row binary search (idle-lane work, independent of scan stores)
        if (t < 64 && b < 128) {
            int row = b * 64 + t;
            float f1 = g_f1[row];
            float tt = -f1;
            int lo = 0, hi2 = N;           // p = #{ f2s <= -f1 }
            while (lo < hi2) {
                int mid = (lo + hi2) >> 1;
                if (g_f2s[mid] <= tt) lo = mid + 1; else hi2 = mid;
            }
            g_p[row] = lo;
            g_c[row] = expf((ALPHA - 1.0f) * f1);
        }
    }
    gbar(gen);

    // ===== Phase F: tiled transpose [d][k] -> [k][d] (+ zero pad rows) ======
    {
        if (b == 128 && t < 64) g_Shi[N * D + t] = 0.f;   // Shi row N
        if (b == 129 && t < 64) g_Plo[t] = 0.f;           // Plo row 0
        float* tile = (float*)sbuf;                       // [64][65]
        for (int tile_id = b; tile_id < 256; tile_id += NBLK) {
            bool hiA = tile_id < 128;
            int k0 = (tile_id & 127) * 64;
            const float* src = hiA ? g_SThi : g_STlo;
            __syncthreads();                              // reuse guard
            {
                int d = t >> 4, kq = (t & 15) * 4;        // coalesced read along k
                float4 sv = *(const float4*)&src[(size_t)d * N + k0 + kq];
                tile[(kq + 0) * 65 + d] = sv.x;
                tile[(kq + 1) * 65 + d] = sv.y;
                tile[(kq + 2) * 65 + d] = sv.z;
                tile[(kq + 3) * 65 + d] = sv.w;
            }
            __syncthreads();
            {
                int kk = t >> 4, dq = (t & 15) * 4;       // coalesced write along d
                float4 ov = make_float4(tile[kk * 65 + dq + 0],
                                        tile[kk * 65 + dq + 1],
                                        tile[kk * 65 + dq + 2],
                                        tile[kk * 65 + dq + 3]);
                if (hiA) *(float4*)&g_Shi[(k0 + kk) * D + dq]     = ov;
                else     *(float4*)&g_Plo[(k0 + kk + 1) * D + dq] = ov;
            }
        }
    }
    gbar(gen);

    // ===== Phase G: branchless fp32 combine + ELU ===========================
    {
        const int d = gtid & 63;           // invariant: GSIZE % 64 == 0
        for (int idx = gtid; idx < N * D; idx += GSIZE) {
            int row = idx >> 6;
            int   p = g_p[row];
            float c = g_c[row];
            float num = g_Shi[p * D + d] + c * g_Plo[p * D + d];
            float den = g_pshis[p]       + c * g_pslos[p];
            float v = __fdividef(num, den);
            out[idx] = (v > 0.f) ? v : expm1f(v);
        }
    }
}

// ---------------- launch ----------------------------------------------------
extern "C" void kernel_launch(void* const* d_in, const int* in_sizes, int n_in,
                              void* d_out, int out_size) {
    const float* x  = (const float*)d_in[0];
    const float* Wt = (const float*)d_in[1];
    const float* a1 = (const float*)d_in[2];
    const float* b1 = (const float*)d_in[3];
    const float* a2 = (const float*)d_in[4];
    const float* b2 = (const float*)d_in[5];
    float* out = (float*)d_out;

    k_fused<<<NBLK, NTHR>>>(x, Wt, a1, b1, a2, b2, out);
}

// round 13
// speedup vs baseline: 1.3600x; 1.0173x over previous
#include <cuda_runtime.h>
#include <math.h>

#define N 8192
#define D 64
#define ALPHA 0.2f
#define NB 16384
#define SHIFT 18           // bucket = top 14 bits of order-flipped float key
#define NBLK 130
#define NTHR 1024
#define GSIZE (NBLK * NTHR)

// ---------------- scratch (device globals; no allocation allowed) -----------
__device__ float    g_h[N * D];        // projected features (2 MB)
__device__ float    g_hsT[D * N];      // h, sorted order, TRANSPOSED [d][k] (2 MB)
__device__ float    g_f1[N];
__device__ float    g_f2[N];
__device__ unsigned g_ukey[N];
__device__ int      g_hist[NB];
__device__ int      g_incl[NB];        // block-local inclusive scan of hist
__device__ int      g_btot[16];
__device__ int      g_start[NB + 1];
__device__ int      g_cursor[NB];
__device__ unsigned g_bkey[N];
__device__ int      g_bidx[N];
__device__ float    g_f2s[N];          // f2 sorted ascending
__device__ int      g_ord[N];          // sorted position -> original index
__device__ float    g_ehi[N];          // e^{f2s}
__device__ float    g_elo[N];          // e^{ALPHA*f2s}
__device__ int      g_p[N];            // per-row split point
__device__ float    g_c[N];            // per-row e^{(ALPHA-1) f1}
__device__ float    g_SThi[D * N];     // suffix sums, transposed [d][k] (2 MB)
__device__ float    g_STlo[D * N];     // prefix sums, transposed [d][k] (2 MB)
__device__ float    g_Shi[(N + 1) * D];// SUFFIX sums [k][d]; row N = 0
__device__ float    g_Plo[(N + 1) * D];// PREFIX sums shifted [k][d]; row 0 = 0
__device__ float    g_pshis[N + 1];    // scalar suffix of e^{f2};   [N]=0
__device__ float    g_pslos[N + 1];    // scalar prefix of e^{a f2}; [0]=0

// ---------------- software grid barrier -------------------------------------
__device__ unsigned g_bar_arrive = 0;
__device__ unsigned g_bar_gen    = 0;

__device__ __forceinline__ void gbar(unsigned& gen) {
    __syncthreads();
    if (threadIdx.x == 0) {
        __threadfence();
        unsigned my = gen;
        if (atomicAdd(&g_bar_arrive, 1) == NBLK - 1) {
            g_bar_arrive = 0;          // reset BEFORE release (ordered by fence)
            __threadfence();
            atomicAdd(&g_bar_gen, 1);
        } else {
            while (*(volatile unsigned*)&g_bar_gen == my) __nanosleep(32);
        }
        __threadfence();
        gen = my + 1;
    }
    __syncthreads();
}

// ---------------- the single persistent kernel ------------------------------
__global__ void __launch_bounds__(NTHR, 1) k_fused(
    const float* __restrict__ x,  const float* __restrict__ Wt,
    const float* __restrict__ a1, const float* __restrict__ b1,
    const float* __restrict__ a2, const float* __restrict__ b2,
    float* __restrict__ out)
{
    __shared__ __align__(16) char sbuf[35328];   // A: sWt|sxT|sa1|sa2|sred ; D2/F tile
    __shared__ int    sord[64];
    __shared__ int    sint[32];
    __shared__ double sdbl[32];

    const int t    = threadIdx.x;
    const int b    = blockIdx.x;
    const int gtid = b * NTHR + t;
    const int lane = t & 31, warp = t >> 5;
    unsigned gen = *(volatile unsigned*)&g_bar_gen;   // per-launch snapshot

    // ===== Phase A: projection h = x*Wt, scores f1/f2, key + histogram ======
    // sxT[k][r] (pad 68): per k-iter the x-quad is a 16B warp-broadcast and
    // the w-read is conflict-free 128B — ~2 LDS-cyc per 4 FMA.
    if (b < 128) {
        float* sWt   = (float*)sbuf;                  // [64][64]  16384 B
        float* sxT   = (float*)(sbuf + 16384);        // [64][68]  17408 B
        float* sa1   = (float*)(sbuf + 33792);        // 256 B
        float* sa2   = (float*)(sbuf + 34048);        // 256 B
        float* sred1 = (float*)(sbuf + 34304);        // [32 warps][4 rows]
        float* sred2 = (float*)(sbuf + 34816);
        const int row0 = b * 64;

        for (int i = t; i < D * D; i += NTHR) sWt[i] = Wt[i];
        for (int i = t; i < D * D; i += NTHR) {
            int r = i >> 6, k = i & 63;
            sxT[k * 68 + r] = x[row0 * D + i];
        }
        if (t < D) { sa1[t] = a1[t]; sa2[t] = a2[t]; }
        __syncthreads();

        const int c  = t & 63;                  // output column
        const int rq = (t >> 6) * 4;            // row-quad base (0,4,...,60)

        float acc0 = 0.f, acc1 = 0.f, acc2 = 0.f, acc3 = 0.f;
        #pragma unroll 16
        for (int k = 0; k < D; k++) {
            float  wv = sWt[k * D + c];                    // conflict-free
            float4 xv = *(const float4*)&sxT[k * 68 + rq]; // 16B broadcast
            acc0 = fmaf(xv.x, wv, acc0);
            acc1 = fmaf(xv.y, wv, acc1);
            acc2 = fmaf(xv.z, wv, acc2);
            acc3 = fmaf(xv.w, wv, acc3);
        }
        g_h[(row0 + rq + 0) * D + c] = acc0;    // coalesced per row
        g_h[(row0 + rq + 1) * D + c] = acc1;
        g_h[(row0 + rq + 2) * D + c] = acc2;
        g_h[(row0 + rq + 3) * D + c] = acc3;

        float a1c = sa1[c], a2c = sa2[c];
        float q10 = acc0 * a1c, q11 = acc1 * a1c, q12 = acc2 * a1c, q13 = acc3 * a1c;
        float q20 = acc0 * a2c, q21 = acc1 * a2c, q22 = acc2 * a2c, q23 = acc3 * a2c;
        #pragma unroll
        for (int off = 16; off > 0; off >>= 1) {
            q10 += __shfl_down_sync(0xffffffffu, q10, off);
            q11 += __shfl_down_sync(0xffffffffu, q11, off);
            q12 += __shfl_down_sync(0xffffffffu, q12, off);
            q13 += __shfl_down_sync(0xffffffffu, q13, off);
            q20 += __shfl_down_sync(0xffffffffu, q20, off);
            q21 += __shfl_down_sync(0xffffffffu, q21, off);
            q22 += __shfl_down_sync(0xffffffffu, q22, off);
            q23 += __shfl_down_sync(0xffffffffu, q23, off);
        }
        if (lane == 0) {
            sred1[warp * 4 + 0] = q10; sred1[warp * 4 + 1] = q11;
            sred1[warp * 4 + 2] = q12; sred1[warp * 4 + 3] = q13;
            sred2[warp * 4 + 0] = q20; sred2[warp * 4 + 1] = q21;
            sred2[warp * 4 + 2] = q22; sred2[warp * 4 + 3] = q23;
        }
        __syncthreads();
        if (t < 64) {
            int rg = t >> 2, rr = t & 3;        // row = rg*4 + rr
            int w0 = rg * 2, w1 = w0 + 1;       // the two warps covering c 0..63
            float f1v = sred1[w0 * 4 + rr] + sred1[w1 * 4 + rr] + b1[0];
            float f2v = sred2[w0 * 4 + rr] + sred2[w1 * 4 + rr] + b2[0];
            int row = row0 + rg * 4 + rr;
            g_f1[row] = f1v;
            g_f2[row] = f2v;
            unsigned u = __float_as_uint(f2v);
            u ^= (u >> 31) ? 0xFFFFFFFFu : 0x80000000u;
            g_ukey[row] = u;
            atomicAdd(&g_hist[u >> SHIFT], 1);
        }
    }
    gbar(gen);

    // ===== Phase B1: per-block inclusive scan of histogram (16 blocks) ======
    if (b < 16) {
        int i = b * NTHR + t;
        int v = g_hist[i];
        int s = v;
        #pragma unroll
        for (int off = 1; off < 32; off <<= 1) {
            int o = __shfl_up_sync(0xffffffffu, s, off);
            if (lane >= off) s += o;
        }
        if (lane == 31) sint[warp] = s;
        __syncthreads();
        if (t < 32) {
            int w2 = sint[t];
            #pragma unroll
            for (int off = 1; off < 32; off <<= 1) {
                int o = __shfl_up_sync(0xffffffffu, w2, off);
                if (t >= off) w2 += o;
            }
            sint[t] = w2;
        }
        __syncthreads();
        int incl = s + (warp ? sint[warp - 1] : 0);
        g_incl[i] = incl;
        if (t == NTHR - 1) g_btot[b] = incl;
    }
    gbar(gen);

    // ===== Phase B3: global offsets -> start/cursor =========================
    if (b < 16) {
        int off = 0;
        #pragma unroll
        for (int j = 0; j < 16; j++) if (j < b) off += g_btot[j];
        int i = b * NTHR + t;
        int excl = off + g_incl[i] - g_hist[i];
        g_start[i]  = excl;
        g_cursor[i] = excl;
    }
    if (b == 0 && t == 0) g_start[NB] = N;
    gbar(gen);

    // ===== Phase C: scatter (128 blocks x 64) + re-zero histogram ===========
    if (b < 128) {
        if (t < 64) {
            int i = b * 64 + t;
            unsigned u = g_ukey[i];
            int pos = atomicAdd(&g_cursor[u >> SHIFT], 1);
            g_bkey[pos] = u;
            g_bidx[pos] = i;
        } else if (t < 192) {
            g_hist[b * 128 + (t - 64)] = 0;
        }
    }
    gbar(gen);

    // ===== Phase D: rank within bucket (16 threads/element) =================
    {
        int el  = gtid >> 4;           // 0..8319
        int seg = gtid & 15;
        if (el < N) {
            unsigned u = g_bkey[el];
            int i  = g_bidx[el];
            int bk = u >> SHIFT;
            int st = g_start[bk], en = g_start[bk + 1];
            int rank = 0;
            for (int j = st + seg; j < en; j += 16) {
                unsigned kj = g_bkey[j];
                rank += (kj < u) || (kj == u && g_bidx[j] < i);
            }
            #pragma unroll
            for (int off = 8; off > 0; off >>= 1)
                rank += __shfl_down_sync(0xffffffffu, rank, off, 16);
            if (seg == 0) {
                rank += st;
                float f2v = g_f2[i];
                g_f2s[rank] = f2v;
                g_ord[rank] = i;
                g_ehi[rank] = expf(f2v);
                g_elo[rank] = expf(ALPHA * f2v);
            }
        }
    }
    gbar(gen);

    // ===== Phase D2: smem-tiled permuted transpose h -> g_hsT[d][k] =========
    if (b < 128) {
        float* tile = (float*)sbuf;                // [64][65]
        const int k0 = b * 64;
        if (t < 64) sord[t] = g_ord[k0 + t];
        __syncthreads();
        {
            int kk = t >> 4, l4 = (t & 15) * 4;    // coalesced-ish row load
            float4 hv = *(const float4*)&g_h[sord[kk] * D + l4];
            tile[kk * 65 + l4 + 0] = hv.x;
            tile[kk * 65 + l4 + 1] = hv.y;
            tile[kk * 65 + l4 + 2] = hv.z;
            tile[kk * 65 + l4 + 3] = hv.w;
        }
        __syncthreads();
        {
            int d = t >> 4, kq = (t & 15) * 4;     // coalesced write along k
            float4 ov = make_float4(tile[(kq + 0) * 65 + d],
                                    tile[(kq + 1) * 65 + d],
                                    tile[(kq + 2) * 65 + d],
                                    tile[(kq + 3) * 65 + d]);
            *(float4*)&g_hsT[d * N + k0 + kq] = ov;
        }
    }
    gbar(gen);

    // ===== Phase E: 130 directional fp64-accum scans -> TRANSPOSED fp32 =====
    // hi blocks (b<64 dims, b==128 scalar): SUFFIX -> g_SThi / g_pshis
    // lo blocks (64..127, b==129 scalar):  PREFIX -> g_STlo / g_pslos
    if (b < 130) {
        bool scalar = (b >= 128);
        bool hi = (b < 64) || (b == 128);
        int dim = scalar ? 0 : (hi ? b : b - 64);
        const float* e    = hi ? g_ehi : g_elo;
        const float* hrow = g_hsT + (size_t)dim * N;

        int k0 = t * 8;
        double v[8];
        double run = 0.0;
        if (hi) {                      // local SUFFIX within chunk (j desc)
            #pragma unroll
            for (int j = 7; j >= 0; j--) {
                double val = (double)e[k0 + j];
                if (!scalar) val *= (double)hrow[k0 + j];
                run += val;
                v[j] = run;
            }
        } else {                       // local PREFIX within chunk (j asc)
            #pragma unroll
            for (int j = 0; j < 8; j++) {
                double val = (double)e[k0 + j];
                if (!scalar) val *= (double)hrow[k0 + j];
                run += val;
                v[j] = run;
            }
        }
        double w = run;
        if (hi) {                      // reverse inclusive scan across lanes
            #pragma unroll
            for (int off = 1; off < 32; off <<= 1) {
                double o = __shfl_down_sync(0xffffffffu, w, off);
                if (lane + off < 32) w += o;
            }
            if (lane == 0) sdbl[warp] = w;
            __syncthreads();
            if (t < 32) {
                double x2 = sdbl[t];
                #pragma unroll
                for (int off = 1; off < 32; off <<= 1) {
                    double o = __shfl_down_sync(0xffffffffu, x2, off);
                    if (t + off < 32) x2 += o;
                }
                sdbl[t] = x2;
            }
            __syncthreads();
            double base = (w - run) + (warp < 31 ? sdbl[warp + 1] : 0.0);
            if (scalar) {
                #pragma unroll
                for (int j = 0; j < 8; j++) g_pshis[k0 + j] = (float)(base + v[j]);
                if (t == 0) g_pshis[N] = 0.f;
            } else {
                float4 s0 = make_float4((float)(base + v[0]), (float)(base + v[1]),
                                        (float)(base + v[2]), (float)(base + v[3]));
                float4 s1 = make_float4((float)(base + v[4]), (float)(base + v[5]),
                                        (float)(base + v[6]), (float)(base + v[7]));
                *(float4*)&g_SThi[(size_t)dim * N + k0]     = s0;
                *(float4*)&g_SThi[(size_t)dim * N + k0 + 4] = s1;
            }
        } else {                       // forward inclusive scan across lanes
            #pragma unroll
            for (int off = 1; off < 32; off <<= 1) {
                double o = __shfl_up_sync(0xffffffffu, w, off);
                if (lane >= off) w += o;
            }
            if (lane == 31) sdbl[warp] = w;
            __syncthreads();
            if (t < 32) {
                double x2 = sdbl[t];
                #pragma unroll
                for (int off = 1; off < 32; off <<= 1) {
                    double o = __shfl_up_sync(0xffffffffu, x2, off);
                    if (t >= off) x2 += o;
                }
                sdbl[t] = x2;
            }
            __syncthreads();
            double base = (w - run) + (warp ? sdbl[warp - 1] : 0.0);
            if (scalar) {              // shifted: pslos[k+1] = incl prefix
                #pragma unroll
                for (int j = 0; j < 8; j++) g_pslos[k0 + j + 1] = (float)(base + v[j]);
                if (t == 0) g_pslos[0] = 0.f;
            } else {                   // unshifted transposed; shift applied in F
                float4 s0 = make_float4((float)(base + v[0]), (float)(base + v[1]),
                                        (float)(base + v[2]), (float)(base + v[3]));
                float4 s1 = make_float4((float)(base + v[4]), (float)(base + v[5]),
                                        (float)(base + v[6]), (float)(base + v[7]));
                *(float4*)&g_STlo[(size_t)dim * N + k0]     = s0;
                *(float4*)&g_STlo[(size_t)dim * N + k0 + 4] = s1;
            }
        }

        // per-row binary search (idle-lane work, independent of scan stores)
        if (t < 64 && b < 128) {
            int row = b * 64 + t;
            float f1 = g_f1[row];
            float tt = -f1;
            int lo = 0, hi2 = N;           // p = #{ f2s <= -f1 }
            while (lo < hi2) {
                int mid = (lo + hi2) >> 1;
                if (g_f2s[mid] <= tt) lo = mid + 1; else hi2 = mid;
            }
            g_p[row] = lo;
            g_c[row] = expf((ALPHA - 1.0f) * f1);
        }
    }
    gbar(gen);

    // ===== Phase F: tiled transpose [d][k] -> [k][d] (+ zero pad rows) ======
    {
        if (b == 128 && t < 64) g_Shi[N * D + t] = 0.f;   // Shi row N
        if (b == 129 && t < 64) g_Plo[t] = 0.f;           // Plo row 0
        float* tile = (float*)sbuf;                       // [64][65]
        for (int tile_id = b; tile_id < 256; tile_id += NBLK) {
            bool hiA = tile_id < 128;
            int k0 = (tile_id & 127) * 64;
            const float* src = hiA ? g_SThi : g_STlo;
            __syncthreads();                              // reuse guard
            {
                int d = t >> 4, kq = (t & 15) * 4;        // coalesced read along k
                float4 sv = *(const float4*)&src[(size_t)d * N + k0 + kq];
                tile[(kq + 0) * 65 + d] = sv.x;
                tile[(kq + 1) * 65 + d] = sv.y;
                tile[(kq + 2) * 65 + d] = sv.z;
                tile[(kq + 3) * 65 + d] = sv.w;
            }
            __syncthreads();
            {
                int kk = t >> 4, dq = (t & 15) * 4;       // coalesced write along d
                float4 ov = make_float4(tile[kk * 65 + dq + 0],
                                        tile[kk * 65 + dq + 1],
                                        tile[kk * 65 + dq + 2],
                                        tile[kk * 65 + dq + 3]);
                if (hiA) *(float4*)&g_Shi[(k0 + kk) * D + dq]     = ov;
                else     *(float4*)&g_Plo[(k0 + kk + 1) * D + dq] = ov;
            }
        }
    }
    gbar(gen);

    // ===== Phase G: branchless fp32 combine + ELU ===========================
    {
        const int d = gtid & 63;           // invariant: GSIZE % 64 == 0
        for (int idx = gtid; idx < N * D; idx += GSIZE) {
            int row = idx >> 6;
            int   p = g_p[row];
            float c = g_c[row];
            float num = g_Shi[p * D + d] + c * g_Plo[p * D + d];
            float den = g_pshis[p]       + c * g_pslos[p];
            float v = __fdividef(num, den);
            out[idx] = (v > 0.f) ? v : expm1f(v);
        }
    }
}

// ---------------- launch ----------------------------------------------------
extern "C" void kernel_launch(void* const* d_in, const int* in_sizes, int n_in,
                              void* d_out, int out_size) {
    const float* x  = (const float*)d_in[0];
    const float* Wt = (const float*)d_in[1];
    const float* a1 = (const float*)d_in[2];
    const float* b1 = (const float*)d_in[3];
    const float* a2 = (const float*)d_in[4];
    const float* b2 = (const float*)d_in[5];
    float* out = (float*)d_out;

    k_fused<<<NBLK, NTHR>>>(x, Wt, a1, b1, a2, b2, out);
}